// round 2
// baseline (speedup 1.0000x reference)
#include <cuda_runtime.h>
#include <cuda_bf16.h>
#include <math.h>

// ---------------------------------------------------------------------------
// Model: xDeepFM forward.
//   B=1024, NUM_NUMERIC=13, NUM_CAT=26, CARD=1000, M=39, D=10, F=26013
//   CIN units 200,200,200 ; DNN 400,400
//
// Decomposition:
//   r = b*10 + d  (R = 10240 "rows")
//   E'  : (R, 39)      per-(b,d) field embeddings
//   CIN layer:  Out[r,h] = sum_i E'[r,i] * sum_j C[r,j] * W[(i*H+j)*200 + h]
//   => one GEMM per layer with A generated on the fly from E' and C.
// ---------------------------------------------------------------------------

#define Bsz 1024
#define NUM_NUMERIC 13
#define NUM_CAT 26
#define CARD 1000
#define Mfld 39
#define Demb 10
#define Ffeat 26013
#define Rrows (Bsz * Demb)   // 10240

// ----------------------------- scratch (static; no allocs allowed) ----------
__device__ float g_E_dm[Rrows * Mfld];      // (10240, 39)   row r=b*10+d, col=field
__device__ float g_E_flat[Bsz * Mfld * Demb]; // (1024, 390) DNN input
__device__ float g_lin[Bsz];
__device__ float g_cin0[Rrows * 200];
__device__ float g_cin1[Rrows * 200];
__device__ float g_cin2[Rrows * 200];
__device__ float g_cinlogit[Bsz];
__device__ float g_h0[Bsz * 400];
__device__ float g_h1[Bsz * 400];

// ----------------------------- helpers --------------------------------------
__device__ __forceinline__ void cp_async16(float* dst_smem, const float* src_gmem) {
    unsigned s = (unsigned)__cvta_generic_to_shared(dst_smem);
    asm volatile("cp.async.cg.shared.global [%0], [%1], 16;\n" :: "r"(s), "l"(src_gmem));
}

// ===========================================================================
// Kernel 1: embeddings + linear logit.
// Grid: 128 blocks x 256 threads. Each block = 8 batch rows (1 warp per row).
// Per categorical field, W_cat[f] staged in shared (transposed [d][1000]).
// ===========================================================================
__global__ void embed_kernel(const float* __restrict__ x,
                             const float* __restrict__ w_lin,
                             const float* __restrict__ W_num,
                             const float* __restrict__ W_cat) {
    __shared__ float Wf[Demb * CARD];  // 40 KB, [d][c]

    const int tid  = threadIdx.x;
    const int warp = tid >> 5;
    const int lane = tid & 31;
    const int b    = blockIdx.x * 8 + warp;
    const float* xr = x + (size_t)b * Ffeat;

    float linacc = 0.0f;

    // numeric fields: E[b,f,d] = x[b,f] * W_num[f,d]
    if (lane < NUM_NUMERIC) {
        float xv = xr[lane];
        linacc += xv * w_lin[lane];
        #pragma unroll
        for (int d = 0; d < Demb; ++d) {
            float v = xv * W_num[lane * Demb + d];
            g_E_flat[b * (Mfld * Demb) + lane * Demb + d] = v;
            g_E_dm[(b * Demb + d) * Mfld + lane] = v;
        }
    }

    for (int f = 0; f < NUM_CAT; ++f) {
        __syncthreads();
        // stage W_cat[f] transposed: Wf[d*1000 + c]
        for (int idx = tid; idx < CARD * Demb; idx += 256) {
            int c = idx / Demb, d = idx - c * Demb;
            Wf[d * CARD + c] = W_cat[(size_t)f * CARD * Demb + idx];
        }
        __syncthreads();

        float acc[Demb];
        #pragma unroll
        for (int d = 0; d < Demb; ++d) acc[d] = 0.0f;

        const float* xf = xr + NUM_NUMERIC + f * CARD;
        const float* wl = w_lin + NUM_NUMERIC + f * CARD;
        for (int c = lane; c < CARD; c += 32) {
            float xv = xf[c];
            linacc += xv * wl[c];
            #pragma unroll
            for (int d = 0; d < Demb; ++d) acc[d] += xv * Wf[d * CARD + c];
        }
        // warp reduce the 10 accumulators
        #pragma unroll
        for (int d = 0; d < Demb; ++d) {
            #pragma unroll
            for (int off = 16; off > 0; off >>= 1)
                acc[d] += __shfl_down_sync(0xffffffffu, acc[d], off);
        }
        if (lane == 0) {
            int fld = NUM_NUMERIC + f;
            #pragma unroll
            for (int d = 0; d < Demb; ++d) {
                float v = acc[d];
                g_E_flat[b * (Mfld * Demb) + fld * Demb + d] = v;
                g_E_dm[(b * Demb + d) * Mfld + fld] = v;
            }
        }
    }

    #pragma unroll
    for (int off = 16; off > 0; off >>= 1)
        linacc += __shfl_down_sync(0xffffffffu, linacc, off);
    if (lane == 0) g_lin[b] = linacc;
}

// ===========================================================================
// Kernel 2: CIN layer GEMM.
//   Out[r, n] = bias[n] + sum_i E'[r,i] * sum_j C[r,j] * W[(i*HIN+j)*200 + n]
// Block: BM=128 rows x BN=40 cols, 256 threads (tx=8 -> TN=5, ty=32 -> TM=4).
// C tile (transposed) + E' tile persistent in shared; W streamed per-i with
// double-buffered cp.async.
// ===========================================================================
template <int HIN>
__global__ void cin_kernel(const float* __restrict__ Cmat,
                           const float* __restrict__ W,
                           const float* __restrict__ bias,
                           float* __restrict__ Out) {
    extern __shared__ float sm[];
    float* Cs = sm;                         // [HIN][128] transposed
    float* Es = Cs + HIN * 128;             // [39][128] transposed
    float* Ws = Es + Mfld * 128;            // [2][HIN][40]

    const int tid  = threadIdx.x;
    const int row0 = blockIdx.x * 128;
    const int n0   = blockIdx.y * 40;

    // load C tile (transposed). global reads coalesced along j.
    for (int idx = tid; idx < HIN * 128; idx += 256) {
        int m = idx / HIN, j = idx - m * HIN;
        Cs[j * 128 + m] = Cmat[(size_t)(row0 + m) * HIN + j];
    }
    // load E' tile (transposed)
    for (int idx = tid; idx < Mfld * 128; idx += 256) {
        int m = idx / Mfld, i = idx - m * Mfld;
        Es[i * 128 + m] = g_E_dm[(size_t)(row0 + m) * Mfld + i];
    }

    // stage W for i=0 into buffer 0
    {
        const float* src = W + (size_t)0 * HIN * 200 + n0;
        for (int c = tid; c < HIN * 10; c += 256) {
            int j = c / 10, q4 = c - j * 10;
            cp_async16(Ws + j * 40 + q4 * 4, src + (size_t)j * 200 + q4 * 4);
        }
        asm volatile("cp.async.commit_group;\n" ::: "memory");
    }
    __syncthreads();

    const int tx = tid & 7;        // n-group: n = n0 + tx*5 + q
    const int ty = tid >> 3;       // m-group: r = row0 + ty*4 + m

    float acc[4][5];
    #pragma unroll
    for (int m = 0; m < 4; ++m)
        #pragma unroll
        for (int q = 0; q < 5; ++q) acc[m][q] = 0.0f;

    for (int i = 0; i < Mfld; ++i) {
        if (i + 1 < Mfld) {
            const float* src = W + (size_t)(i + 1) * HIN * 200 + n0;
            float* dst = Ws + ((i + 1) & 1) * (HIN * 40);
            for (int c = tid; c < HIN * 10; c += 256) {
                int j = c / 10, q4 = c - j * 10;
                cp_async16(dst + j * 40 + q4 * 4, src + (size_t)j * 200 + q4 * 4);
            }
            asm volatile("cp.async.commit_group;\n" ::: "memory");
            asm volatile("cp.async.wait_group 1;\n" ::: "memory");
        } else {
            asm volatile("cp.async.wait_group 0;\n" ::: "memory");
        }
        __syncthreads();

        const float* Wb = Ws + (i & 1) * (HIN * 40) + tx * 5;

        float4 e4 = *reinterpret_cast<const float4*>(Es + i * 128 + (ty << 2));
        float ev[4] = {e4.x, e4.y, e4.z, e4.w};

        float inner[4][5];
        #pragma unroll
        for (int m = 0; m < 4; ++m)
            #pragma unroll
            for (int q = 0; q < 5; ++q) inner[m][q] = 0.0f;

        #pragma unroll 4
        for (int j = 0; j < HIN; ++j) {
            float4 c4 = *reinterpret_cast<const float4*>(Cs + j * 128 + (ty << 2));
            float cv[4] = {c4.x, c4.y, c4.z, c4.w};
            float wv[5];
            #pragma unroll
            for (int q = 0; q < 5; ++q) wv[q] = Wb[j * 40 + q];
            #pragma unroll
            for (int m = 0; m < 4; ++m)
                #pragma unroll
                for (int q = 0; q < 5; ++q)
                    inner[m][q] += cv[m] * wv[q];
        }

        #pragma unroll
        for (int m = 0; m < 4; ++m)
            #pragma unroll
            for (int q = 0; q < 5; ++q)
                acc[m][q] += ev[m] * inner[m][q];

        __syncthreads();  // protect buffer about to be overwritten next iter
    }

    // epilogue: add bias, store
    #pragma unroll
    for (int m = 0; m < 4; ++m) {
        int r = row0 + (ty << 2) + m;
        #pragma unroll
        for (int q = 0; q < 5; ++q) {
            int n = n0 + tx * 5 + q;
            Out[(size_t)r * 200 + n] = acc[m][q] + bias[n];
        }
    }
}

// ===========================================================================
// Kernel 3: CIN pooling + cin linear (no bias; added in final kernel)
//   cin_logit[b] = sum_l sum_h (sum_d Out_l[(b*10+d),h]) * cin_lin_w[l*200+h]
// ===========================================================================
__global__ void pool_kernel(const float* __restrict__ cin_lin_w) {
    const int b = blockIdx.x;
    const int tid = threadIdx.x;
    const float* outs[3];
    outs[0] = g_cin0; outs[1] = g_cin1; outs[2] = g_cin2;

    float acc = 0.0f;
    // j = l*2000 + d*200 + h  -> consecutive tid = consecutive h (coalesced)
    for (int j = tid; j < 3 * Demb * 200; j += 256) {
        int l = j / 2000;
        int rem = j - l * 2000;
        int d = rem / 200;
        int h = rem - d * 200;
        acc += outs[l][(size_t)(b * Demb + d) * 200 + h] * cin_lin_w[l * 200 + h];
    }
    __shared__ float red[256];
    red[tid] = acc;
    __syncthreads();
    for (int s = 128; s > 0; s >>= 1) {
        if (tid < s) red[tid] += red[tid + s];
        __syncthreads();
    }
    if (tid == 0) g_cinlogit[b] = red[0];
}

// ===========================================================================
// Kernel 4: DNN GEMM + optional relu.  C(1024 x 400) = act(A(1024xK) @ W(Kx400) + b)
// BM=64, BN=40, BK=16, 256 threads (tx=8 -> TN=5, ty=32 -> TM=2)
// ===========================================================================
__global__ void dnn_gemm(const float* __restrict__ A,
                         const float* __restrict__ W,
                         const float* __restrict__ bias,
                         float* __restrict__ Out,
                         int K, int relu) {
    __shared__ float As[16 * 64];   // [kk][r]
    __shared__ float Bs[16 * 40];   // [kk][q]

    const int tid = threadIdx.x;
    const int row0 = blockIdx.x * 64;
    const int n0 = blockIdx.y * 40;
    const int tx = tid & 7;
    const int ty = tid >> 3;
    const int N = 400;

    float acc[2][5];
    #pragma unroll
    for (int m = 0; m < 2; ++m)
        #pragma unroll
        for (int q = 0; q < 5; ++q) acc[m][q] = 0.0f;

    for (int k0 = 0; k0 < K; k0 += 16) {
        __syncthreads();
        // A tile: 64 rows x 16 k
        for (int idx = tid; idx < 64 * 16; idx += 256) {
            int r = idx >> 4, kk = idx & 15;
            int k = k0 + kk;
            As[kk * 64 + r] = (k < K) ? A[(size_t)(row0 + r) * K + k] : 0.0f;
        }
        // W tile: 16 k x 40 n
        for (int idx = tid; idx < 16 * 40; idx += 256) {
            int kk = idx / 40, q = idx - kk * 40;
            int k = k0 + kk;
            Bs[kk * 40 + q] = (k < K) ? W[(size_t)k * N + n0 + q] : 0.0f;
        }
        __syncthreads();

        #pragma unroll
        for (int kk = 0; kk < 16; ++kk) {
            float a0 = As[kk * 64 + ty * 2 + 0];
            float a1 = As[kk * 64 + ty * 2 + 1];
            float wv[5];
            #pragma unroll
            for (int q = 0; q < 5; ++q) wv[q] = Bs[kk * 40 + tx * 5 + q];
            #pragma unroll
            for (int q = 0; q < 5; ++q) {
                acc[0][q] += a0 * wv[q];
                acc[1][q] += a1 * wv[q];
            }
        }
    }

    #pragma unroll
    for (int m = 0; m < 2; ++m) {
        int r = row0 + ty * 2 + m;
        #pragma unroll
        for (int q = 0; q < 5; ++q) {
            int n = n0 + tx * 5 + q;
            float v = acc[m][q] + bias[n];
            if (relu) v = fmaxf(v, 0.0f);
            Out[(size_t)r * N + n] = v;
        }
    }
}

// ===========================================================================
// Kernel 5: final dot (dnn linear) + combine all logits + sigmoid
// ===========================================================================
__global__ void final_kernel(const float* __restrict__ b_lin,
                             const float* __restrict__ cin_lin_b,
                             const float* __restrict__ dnn_lin_w,
                             const float* __restrict__ dnn_lin_b,
                             const float* __restrict__ pred_b,
                             float* __restrict__ out) {
    const int b = blockIdx.x;
    const int tid = threadIdx.x;
    float acc = 0.0f;
    for (int k = tid; k < 400; k += 128)
        acc += g_h1[(size_t)b * 400 + k] * dnn_lin_w[k];
    __shared__ float red[128];
    red[tid] = acc;
    __syncthreads();
    for (int s = 64; s > 0; s >>= 1) {
        if (tid < s) red[tid] += red[tid + s];
        __syncthreads();
    }
    if (tid == 0) {
        float z = g_lin[b] + b_lin[0]
                + g_cinlogit[b] + cin_lin_b[0]
                + red[0] + dnn_lin_b[0]
                + pred_b[0];
        out[b] = 1.0f / (1.0f + expf(-z));
    }
}

// ===========================================================================
// host launcher
// ===========================================================================
extern "C" void kernel_launch(void* const* d_in, const int* in_sizes, int n_in,
                              void* d_out, int out_size) {
    const float* x         = (const float*)d_in[0];
    const float* w_lin     = (const float*)d_in[1];
    const float* b_lin     = (const float*)d_in[2];
    const float* W_num     = (const float*)d_in[3];
    const float* W_cat     = (const float*)d_in[4];
    const float* cin_w0    = (const float*)d_in[5];
    const float* cin_b0    = (const float*)d_in[6];
    const float* cin_w1    = (const float*)d_in[7];
    const float* cin_b1    = (const float*)d_in[8];
    const float* cin_w2    = (const float*)d_in[9];
    const float* cin_b2    = (const float*)d_in[10];
    const float* cin_lin_w = (const float*)d_in[11];
    const float* cin_lin_b = (const float*)d_in[12];
    const float* dnn_w0    = (const float*)d_in[13];
    const float* dnn_b0    = (const float*)d_in[14];
    const float* dnn_w1    = (const float*)d_in[15];
    const float* dnn_b1    = (const float*)d_in[16];
    const float* dnn_lin_w = (const float*)d_in[17];
    const float* dnn_lin_b = (const float*)d_in[18];
    const float* pred_b    = (const float*)d_in[19];
    float* out = (float*)d_out;

    float *p_E_dm, *p_E_flat, *p_cin0, *p_cin1, *p_cin2, *p_h0, *p_h1;
    cudaGetSymbolAddress((void**)&p_E_dm,   g_E_dm);
    cudaGetSymbolAddress((void**)&p_E_flat, g_E_flat);
    cudaGetSymbolAddress((void**)&p_cin0,   g_cin0);
    cudaGetSymbolAddress((void**)&p_cin1,   g_cin1);
    cudaGetSymbolAddress((void**)&p_cin2,   g_cin2);
    cudaGetSymbolAddress((void**)&p_h0,     g_h0);
    cudaGetSymbolAddress((void**)&p_h1,     g_h1);

    const int SMEM39  = (39 * 128 + Mfld * 128 + 2 * 39 * 40) * 4;
    const int SMEM200 = (200 * 128 + Mfld * 128 + 2 * 200 * 40) * 4;
    cudaFuncSetAttribute(cin_kernel<39>,  cudaFuncAttributeMaxDynamicSharedMemorySize, SMEM39);
    cudaFuncSetAttribute(cin_kernel<200>, cudaFuncAttributeMaxDynamicSharedMemorySize, SMEM200);

    // 1. embeddings + linear
    embed_kernel<<<Bsz / 8, 256>>>(x, w_lin, W_num, W_cat);

    // 2. CIN layers (Khatri-Rao GEMMs)
    dim3 cgrid(Rrows / 128, 200 / 40);
    cin_kernel<39><<<cgrid, 256, SMEM39>>>(p_E_dm, cin_w0, cin_b0, p_cin0);
    cin_kernel<200><<<cgrid, 256, SMEM200>>>(p_cin0, cin_w1, cin_b1, p_cin1);
    cin_kernel<200><<<cgrid, 256, SMEM200>>>(p_cin1, cin_w2, cin_b2, p_cin2);

    // 3. CIN pooling + linear
    pool_kernel<<<Bsz, 256>>>(cin_lin_w);

    // 4. DNN
    dim3 dgrid(Bsz / 64, 400 / 40);
    dnn_gemm<<<dgrid, 256>>>(p_E_flat, dnn_w0, dnn_b0, p_h0, Mfld * Demb, 1);
    dnn_gemm<<<dgrid, 256>>>(p_h0, dnn_w1, dnn_b1, p_h1, 400, 1);

    // 5. final combine + sigmoid
    final_kernel<<<Bsz, 128>>>(b_lin, cin_lin_b, dnn_lin_w, dnn_lin_b, pred_b, out);
}

// round 5
// speedup vs baseline: 1.6688x; 1.6688x over previous
#include <cuda_runtime.h>
#include <cuda_bf16.h>
#include <mma.h>
#include <math.h>
#include <stdint.h>

using namespace nvcuda;

// ---------------------------------------------------------------------------
// xDeepFM forward. CIN layers as WMMA bf16 3-term-split GEMMs (sm_100-legal):
//   r = b*10+d (R=10240 rows)
//   Out[r,h] = bias[h] + sum_{i,j} E'[r,i]*C[r,j]*W[(i*H+j),h]
//   A[r,k]=E'[r,i]*C[r,j] generated on the fly into SMEM (bf16 hi/lo),
//   W pre-split into bf16 hi/lo, padded [KPAD][224].
//   3 terms: AhiWhi + AhiWlo + AloWhi (fp32 accum). K-split across blocks,
//   partial buffers summed (+bias) by small reduce kernels.
// ---------------------------------------------------------------------------

#define Bsz 1024
#define NUM_NUMERIC 13
#define NUM_CAT 26
#define CARD 1000
#define Mfld 39
#define Demb 10
#define Ffeat 26013
#define Rrows (Bsz * Demb)   // 10240

#define NPAD 224
#define KPAD0 1536           // 39*39=1521 padded ; split 3 x 512
#define KPAD1 7840           // 39*200=7800 padded; split 7 x 1120
#define SPLIT0 3
#define SPLIT1 7
#define KPER0 (KPAD0 / SPLIT0)   // 512
#define KPER1 (KPAD1 / SPLIT1)   // 1120
#define PSTR ((size_t)Rrows * NPAD)

// ----------------------------- scratch --------------------------------------
__device__ float g_E_dm[Rrows * Mfld];        // (10240, 39)
__device__ float g_E_flat[Bsz * Mfld * Demb]; // (1024, 390)
__device__ float g_linpart[27 * Bsz];         // 26 cat fields + 1 numeric
__device__ float g_part[SPLIT1 * Rrows * NPAD];  // K-split partial outputs (64MB)
__device__ float g_cin0[Rrows * 200];
__device__ float g_cin1[Rrows * 200];
__device__ float g_cin2[Rrows * 200];
__device__ float g_cinlogit[Bsz];
__device__ float g_h0[Bsz * 400];
__device__ float g_h1[Bsz * 400];

__device__ __nv_bfloat16 g_W0hi[KPAD0 * NPAD];
__device__ __nv_bfloat16 g_W0lo[KPAD0 * NPAD];
__device__ __nv_bfloat16 g_W1hi[KPAD1 * NPAD];
__device__ __nv_bfloat16 g_W1lo[KPAD1 * NPAD];
__device__ __nv_bfloat16 g_W2hi[KPAD1 * NPAD];
__device__ __nv_bfloat16 g_W2lo[KPAD1 * NPAD];

// ----------------------------- helpers --------------------------------------
__device__ __forceinline__ void cp_async16g(void* dst, const void* src) {
    unsigned s = (unsigned)__cvta_generic_to_shared(dst);
    asm volatile("cp.async.cg.shared.global [%0], [%1], 16;\n" :: "r"(s), "l"(src));
}
#define CP_COMMIT() asm volatile("cp.async.commit_group;\n" ::: "memory")
#define CP_WAIT0()  asm volatile("cp.async.wait_group 0;\n" ::: "memory")

// ===========================================================================
// Kernel E1: numeric embeddings + numeric part of linear logit.
// ===========================================================================
__global__ void numeric_kernel(const float* __restrict__ x,
                               const float* __restrict__ w_lin,
                               const float* __restrict__ W_num) {
    const int b = blockIdx.x * 128 + threadIdx.x;
    const float* xr = x + (size_t)b * Ffeat;
    float lin = 0.0f;
    #pragma unroll
    for (int f = 0; f < NUM_NUMERIC; ++f) {
        float xv = xr[f];
        lin += xv * w_lin[f];
        #pragma unroll
        for (int d = 0; d < Demb; ++d) {
            float v = xv * W_num[f * Demb + d];
            g_E_flat[b * (Mfld * Demb) + f * Demb + d] = v;
            g_E_dm[(b * Demb + d) * Mfld + f] = v;
        }
    }
    g_linpart[26 * Bsz + b] = lin;
}

// ===========================================================================
// Kernel E2: categorical embeddings as skinny GEMMs (1024 x 10 x 1000 per
// field) + per-field linear partials.  Grid (8 batch-blocks, 26 fields).
// ===========================================================================
__global__ __launch_bounds__(256)
void cat_kernel(const float* __restrict__ x,
                const float* __restrict__ w_lin,
                const float* __restrict__ W_cat) {
    __shared__ float Xs[64 * 130];   // [c][r], pad 130
    __shared__ float Ws[64 * 10];    // [kk][d]
    __shared__ float Ls[64];

    const int t    = threadIdx.x;
    const int f    = blockIdx.y;
    const int b0   = blockIdx.x * 128;
    const int r    = t & 127;
    const int half = t >> 7;
    const int d0   = half * 5;

    float acc[5] = {0.f, 0.f, 0.f, 0.f, 0.f};
    float lin = 0.0f;

    for (int k0 = 0; k0 < CARD; k0 += 64) {
        const int kc = min(64, CARD - k0);
        __syncthreads();
        for (int idx = t; idx < 128 * 64; idx += 256) {
            int rr = idx >> 6, c = idx & 63;
            float v = (c < kc) ? x[(size_t)(b0 + rr) * Ffeat + NUM_NUMERIC + f * CARD + k0 + c] : 0.0f;
            Xs[c * 130 + rr] = v;
        }
        for (int idx = t; idx < 640; idx += 256) {
            int kk = idx / 10, d = idx - kk * 10;
            Ws[idx] = (kk < kc) ? W_cat[(size_t)(f * CARD + k0 + kk) * Demb + d] : 0.0f;
        }
        if (t < 64) Ls[t] = (t < kc) ? w_lin[NUM_NUMERIC + f * CARD + k0 + t] : 0.0f;
        __syncthreads();

        #pragma unroll 8
        for (int kk = 0; kk < 64; ++kk) {
            float xv = Xs[kk * 130 + r];
            if (half == 0) lin += xv * Ls[kk];
            #pragma unroll
            for (int q = 0; q < 5; ++q) acc[q] += xv * Ws[kk * 10 + d0 + q];
        }
    }

    const int b = b0 + r;
    const int fld = NUM_NUMERIC + f;
    #pragma unroll
    for (int q = 0; q < 5; ++q) {
        int d = d0 + q;
        g_E_flat[b * (Mfld * Demb) + fld * Demb + d] = acc[q];
        g_E_dm[(b * Demb + d) * Mfld + fld] = acc[q];
    }
    if (half == 0) g_linpart[f * Bsz + b] = lin;
}

// ===========================================================================
// Kernel: split W into bf16 hi/lo, layout [k][224], zero-padded.
// ===========================================================================
__global__ void convert_w(const float* __restrict__ W,
                          __nv_bfloat16* __restrict__ Whi,
                          __nv_bfloat16* __restrict__ Wlo,
                          int KTOT, int KPAD) {
    int idx = blockIdx.x * 256 + threadIdx.x;
    if (idx >= KPAD * NPAD) return;
    int k = idx / NPAD;
    int n = idx - k * NPAD;
    float v = (k < KTOT && n < 200) ? W[(size_t)k * 200 + n] : 0.0f;
    __nv_bfloat16 h = __float2bfloat16_rn(v);
    Whi[idx] = h;
    Wlo[idx] = __float2bfloat16_rn(v - __bfloat162float(h));
}

// ===========================================================================
// CIN layer GEMM via WMMA bf16, 3-term split, K-split across blockIdx.y.
// Block: 128 rows x 224 cols, 256 threads = 8 warps (4m x 2n), k16 steps.
// ===========================================================================
template <int HIN, int KPER>
__global__ void __launch_bounds__(256, 1)
cin_wmma(const float* __restrict__ Cmat,
         const __nv_bfloat16* __restrict__ Whi,
         const __nv_bfloat16* __restrict__ Wlo,
         float* __restrict__ part) {
    constexpr int KTOT = 39 * HIN;
    constexpr int NK   = KPER / 16;
    constexpr int CS_BYTES = 128 * HIN * 4;
    constexpr int ES_OFF   = CS_BYTES;
    constexpr int A_OFF    = ((ES_OFF + 128 * 39 * 4 + 1023) / 1024) * 1024;
    constexpr int A_HALF   = 128 * 24 * 2;            // 6144 B (ld=24)
    constexpr int A_BUF    = 2 * A_HALF;              // hi+lo
    constexpr int B_OFF    = A_OFF + 2 * A_BUF;
    constexpr int B_HALF   = 16 * 232 * 2;            // 7424 B (ld=232)
    constexpr int B_BUF    = 2 * B_HALF;

    extern __shared__ char sm[];
    float* Cs = (float*)sm;
    float* Es = (float*)(sm + ES_OFF);

    const int tid  = threadIdx.x;
    const int wid  = tid >> 5;
    const int wm   = wid & 3;        // 4 m-groups of 32 rows
    const int wn   = wid >> 2;       // 2 n-groups of 112 cols
    const int row0 = blockIdx.x * 128;
    const int kbase = blockIdx.y * KPER;

    // ---- prologue: resident C and E tiles (coalesced float4) ----
    {
        const float4* src = (const float4*)(Cmat + (size_t)row0 * HIN);
        float4* dst = (float4*)Cs;
        for (int i = tid; i < 128 * HIN / 4; i += 256) dst[i] = src[i];
        const float4* esrc = (const float4*)(g_E_dm + (size_t)row0 * 39);
        float4* edst = (float4*)Es;
        for (int i = tid; i < 128 * 39 / 4; i += 256) edst[i] = esrc[i];
    }

    auto load_B = [&](int ks, int buf) {
        char* base = sm + B_OFF + buf * B_BUF;
        const int krow0 = kbase + ks * 16;
        for (int idx = tid; idx < 896; idx += 256) {
            int h   = idx / 448;
            int rem = idx - h * 448;
            int kk  = rem / 28;
            int q   = rem - kk * 28;
            const __nv_bfloat16* src = (h ? Wlo : Whi) + (size_t)(krow0 + kk) * NPAD + q * 8;
            cp_async16g(base + h * B_HALF + (kk * 232 + q * 8) * 2, src);
        }
        CP_COMMIT();
    };
    auto gen_A = [&](int ks, int buf) {
        char* Ahi = sm + A_OFF + buf * A_BUF;
        char* Alo = Ahi + A_HALF;
        const int k0b = kbase + ks * 16;
        for (int p = tid; p < 1024; p += 256) {
            int m   = p >> 3;
            int kk2 = (p & 7) << 1;
            int k0  = k0b + kk2;
            float a0 = 0.f, a1 = 0.f;
            if (k0 < KTOT) {
                int i = k0 / HIN, j = k0 - i * HIN;
                a0 = Es[m * 39 + i] * Cs[m * HIN + j];
            }
            if (k0 + 1 < KTOT) {
                int i = (k0 + 1) / HIN, j = (k0 + 1) - i * HIN;
                a1 = Es[m * 39 + i] * Cs[m * HIN + j];
            }
            __nv_bfloat16 h0 = __float2bfloat16_rn(a0);
            __nv_bfloat16 h1 = __float2bfloat16_rn(a1);
            __nv_bfloat16 l0 = __float2bfloat16_rn(a0 - __bfloat162float(h0));
            __nv_bfloat16 l1 = __float2bfloat16_rn(a1 - __bfloat162float(h1));
            uint32_t off = (uint32_t)(m * 24 + kk2) * 2;
            *(uint32_t*)(Ahi + off) = ((uint32_t)__bfloat16_as_ushort(h1) << 16) | __bfloat16_as_ushort(h0);
            *(uint32_t*)(Alo + off) = ((uint32_t)__bfloat16_as_ushort(l1) << 16) | __bfloat16_as_ushort(l0);
        }
    };

    __syncthreads();          // Cs/Es ready
    load_B(0, 0);
    gen_A(0, 0);
    CP_WAIT0();
    __syncthreads();

    wmma::fragment<wmma::accumulator, 16, 16, 16, float> acc[2][7];
    #pragma unroll
    for (int s = 0; s < 2; ++s)
        #pragma unroll
        for (int n = 0; n < 7; ++n) wmma::fill_fragment(acc[s][n], 0.0f);

    for (int ks = 0; ks < NK; ++ks) {
        const int buf = ks & 1;
        if (ks + 1 < NK) {
            load_B(ks + 1, buf ^ 1);   // async, overlaps MMA below
            gen_A(ks + 1, buf ^ 1);
        }

        const __nv_bfloat16* Ahi = (const __nv_bfloat16*)(sm + A_OFF + buf * A_BUF);
        const __nv_bfloat16* Alo = Ahi + A_HALF / 2;
        const __nv_bfloat16* Bhi = (const __nv_bfloat16*)(sm + B_OFF + buf * B_BUF);
        const __nv_bfloat16* Blo = Bhi + B_HALF / 2;

        wmma::fragment<wmma::matrix_a, 16, 16, 16, __nv_bfloat16, wmma::row_major> af[2];
        wmma::fragment<wmma::matrix_b, 16, 16, 16, __nv_bfloat16, wmma::row_major> bfr;

        // term 1: Ahi * Bhi ; term 2: Ahi * Blo
        #pragma unroll
        for (int s = 0; s < 2; ++s)
            wmma::load_matrix_sync(af[s], Ahi + (wm * 32 + s * 16) * 24, 24);
        #pragma unroll
        for (int n = 0; n < 7; ++n) {
            wmma::load_matrix_sync(bfr, Bhi + wn * 112 + n * 16, 232);
            #pragma unroll
            for (int s = 0; s < 2; ++s) wmma::mma_sync(acc[s][n], af[s], bfr, acc[s][n]);
        }
        #pragma unroll
        for (int n = 0; n < 7; ++n) {
            wmma::load_matrix_sync(bfr, Blo + wn * 112 + n * 16, 232);
            #pragma unroll
            for (int s = 0; s < 2; ++s) wmma::mma_sync(acc[s][n], af[s], bfr, acc[s][n]);
        }
        // term 3: Alo * Bhi
        #pragma unroll
        for (int s = 0; s < 2; ++s)
            wmma::load_matrix_sync(af[s], Alo + (wm * 32 + s * 16) * 24, 24);
        #pragma unroll
        for (int n = 0; n < 7; ++n) {
            wmma::load_matrix_sync(bfr, Bhi + wn * 112 + n * 16, 232);
            #pragma unroll
            for (int s = 0; s < 2; ++s) wmma::mma_sync(acc[s][n], af[s], bfr, acc[s][n]);
        }

        CP_WAIT0();
        __syncthreads();
    }

    // ---- epilogue: store partials ----
    float* op = part + (size_t)blockIdx.y * PSTR;
    #pragma unroll
    for (int s = 0; s < 2; ++s)
        #pragma unroll
        for (int n = 0; n < 7; ++n)
            wmma::store_matrix_sync(op + (size_t)(row0 + wm * 32 + s * 16) * NPAD + wn * 112 + n * 16,
                                    acc[s][n], NPAD, wmma::mem_row_major);
}

// ===========================================================================
// Reduce K-split partials (+bias) into the 200-wide layer output.
// ===========================================================================
__global__ void reduce_kernel(const float* __restrict__ bias,
                              float* __restrict__ dst, int S) {
    int idx = blockIdx.x * 256 + threadIdx.x;
    if (idx >= Rrows * 200) return;
    int r = idx / 200;
    int h = idx - r * 200;
    float v = bias[h];
    for (int s = 0; s < S; ++s) v += g_part[(size_t)s * PSTR + (size_t)r * NPAD + h];
    dst[idx] = v;
}

// ===========================================================================
// CIN pooling + cin linear
// ===========================================================================
__global__ void pool_kernel(const float* __restrict__ cin_lin_w) {
    const int b = blockIdx.x;
    const int tid = threadIdx.x;
    const float* outs[3];
    outs[0] = g_cin0; outs[1] = g_cin1; outs[2] = g_cin2;

    float acc = 0.0f;
    for (int j = tid; j < 3 * Demb * 200; j += 256) {
        int l = j / 2000;
        int rem = j - l * 2000;
        int d = rem / 200;
        int h = rem - d * 200;
        acc += outs[l][(size_t)(b * Demb + d) * 200 + h] * cin_lin_w[l * 200 + h];
    }
    __shared__ float red[256];
    red[tid] = acc;
    __syncthreads();
    for (int s = 128; s > 0; s >>= 1) {
        if (tid < s) red[tid] += red[tid + s];
        __syncthreads();
    }
    if (tid == 0) g_cinlogit[b] = red[0];
}

// ===========================================================================
// DNN GEMM + optional relu
// ===========================================================================
__global__ void dnn_gemm(const float* __restrict__ A,
                         const float* __restrict__ W,
                         const float* __restrict__ bias,
                         float* __restrict__ Out,
                         int K, int relu) {
    __shared__ float As[16 * 64];
    __shared__ float Bs[16 * 40];

    const int tid = threadIdx.x;
    const int row0 = blockIdx.x * 64;
    const int n0 = blockIdx.y * 40;
    const int tx = tid & 7;
    const int ty = tid >> 3;
    const int N = 400;

    float acc[2][5];
    #pragma unroll
    for (int m = 0; m < 2; ++m)
        #pragma unroll
        for (int q = 0; q < 5; ++q) acc[m][q] = 0.0f;

    for (int k0 = 0; k0 < K; k0 += 16) {
        __syncthreads();
        for (int idx = tid; idx < 64 * 16; idx += 256) {
            int r = idx >> 4, kk = idx & 15;
            int k = k0 + kk;
            As[kk * 64 + r] = (k < K) ? A[(size_t)(row0 + r) * K + k] : 0.0f;
        }
        for (int idx = tid; idx < 16 * 40; idx += 256) {
            int kk = idx / 40, q = idx - kk * 40;
            int k = k0 + kk;
            Bs[kk * 40 + q] = (k < K) ? W[(size_t)k * N + n0 + q] : 0.0f;
        }
        __syncthreads();

        #pragma unroll
        for (int kk = 0; kk < 16; ++kk) {
            float a0 = As[kk * 64 + ty * 2 + 0];
            float a1 = As[kk * 64 + ty * 2 + 1];
            float wv[5];
            #pragma unroll
            for (int q = 0; q < 5; ++q) wv[q] = Bs[kk * 40 + tx * 5 + q];
            #pragma unroll
            for (int q = 0; q < 5; ++q) {
                acc[0][q] += a0 * wv[q];
                acc[1][q] += a1 * wv[q];
            }
        }
    }

    #pragma unroll
    for (int m = 0; m < 2; ++m) {
        int r = row0 + ty * 2 + m;
        #pragma unroll
        for (int q = 0; q < 5; ++q) {
            int n = n0 + tx * 5 + q;
            float v = acc[m][q] + bias[n];
            if (relu) v = fmaxf(v, 0.0f);
            Out[(size_t)r * N + n] = v;
        }
    }
}

// ===========================================================================
// Final: dnn linear dot + linear-logit partials + combine + sigmoid
// ===========================================================================
__global__ void final_kernel(const float* __restrict__ b_lin,
                             const float* __restrict__ cin_lin_b,
                             const float* __restrict__ dnn_lin_w,
                             const float* __restrict__ dnn_lin_b,
                             const float* __restrict__ pred_b,
                             float* __restrict__ out) {
    const int b = blockIdx.x;
    const int tid = threadIdx.x;
    float acc = 0.0f;
    for (int k = tid; k < 400; k += 128)
        acc += g_h1[(size_t)b * 400 + k] * dnn_lin_w[k];
    for (int f = tid; f < 27; f += 128)
        acc += g_linpart[f * Bsz + b];
    __shared__ float red[128];
    red[tid] = acc;
    __syncthreads();
    for (int s = 64; s > 0; s >>= 1) {
        if (tid < s) red[tid] += red[tid + s];
        __syncthreads();
    }
    if (tid == 0) {
        float z = red[0] + b_lin[0]
                + g_cinlogit[b] + cin_lin_b[0]
                + dnn_lin_b[0] + pred_b[0];
        out[b] = 1.0f / (1.0f + expf(-z));
    }
}

// ===========================================================================
// host launcher
// ===========================================================================
static int smem_cin(int HIN) {
    int es_off = 128 * HIN * 4;
    int a_off = ((es_off + 128 * 39 * 4 + 1023) / 1024) * 1024;
    return a_off + 2 * (2 * 128 * 24 * 2) + 2 * (2 * 16 * 232 * 2);
}

extern "C" void kernel_launch(void* const* d_in, const int* in_sizes, int n_in,
                              void* d_out, int out_size) {
    const float* x         = (const float*)d_in[0];
    const float* w_lin     = (const float*)d_in[1];
    const float* b_lin     = (const float*)d_in[2];
    const float* W_num     = (const float*)d_in[3];
    const float* W_cat     = (const float*)d_in[4];
    const float* cin_w0    = (const float*)d_in[5];
    const float* cin_b0    = (const float*)d_in[6];
    const float* cin_w1    = (const float*)d_in[7];
    const float* cin_b1    = (const float*)d_in[8];
    const float* cin_w2    = (const float*)d_in[9];
    const float* cin_b2    = (const float*)d_in[10];
    const float* cin_lin_w = (const float*)d_in[11];
    const float* cin_lin_b = (const float*)d_in[12];
    const float* dnn_w0    = (const float*)d_in[13];
    const float* dnn_b0    = (const float*)d_in[14];
    const float* dnn_w1    = (const float*)d_in[15];
    const float* dnn_b1    = (const float*)d_in[16];
    const float* dnn_lin_w = (const float*)d_in[17];
    const float* dnn_lin_b = (const float*)d_in[18];
    const float* pred_b    = (const float*)d_in[19];
    float* out = (float*)d_out;

    float *p_E_dm, *p_cin0, *p_cin1, *p_cin2, *p_E_flat, *p_h0, *p_h1, *p_part;
    cudaGetSymbolAddress((void**)&p_E_dm,   g_E_dm);
    cudaGetSymbolAddress((void**)&p_E_flat, g_E_flat);
    cudaGetSymbolAddress((void**)&p_cin0,   g_cin0);
    cudaGetSymbolAddress((void**)&p_cin1,   g_cin1);
    cudaGetSymbolAddress((void**)&p_cin2,   g_cin2);
    cudaGetSymbolAddress((void**)&p_h0,     g_h0);
    cudaGetSymbolAddress((void**)&p_h1,     g_h1);
    cudaGetSymbolAddress((void**)&p_part,   g_part);

    __nv_bfloat16 *p_W0hi, *p_W0lo, *p_W1hi, *p_W1lo, *p_W2hi, *p_W2lo;
    cudaGetSymbolAddress((void**)&p_W0hi, g_W0hi);
    cudaGetSymbolAddress((void**)&p_W0lo, g_W0lo);
    cudaGetSymbolAddress((void**)&p_W1hi, g_W1hi);
    cudaGetSymbolAddress((void**)&p_W1lo, g_W1lo);
    cudaGetSymbolAddress((void**)&p_W2hi, g_W2hi);
    cudaGetSymbolAddress((void**)&p_W2lo, g_W2lo);

    const int SM0 = smem_cin(39);
    const int SM1 = smem_cin(200);
    cudaFuncSetAttribute(cin_wmma<39,  KPER0>, cudaFuncAttributeMaxDynamicSharedMemorySize, SM0);
    cudaFuncSetAttribute(cin_wmma<200, KPER1>, cudaFuncAttributeMaxDynamicSharedMemorySize, SM1);

    // 1. embeddings + linear partials
    numeric_kernel<<<Bsz / 128, 128>>>(x, w_lin, W_num);
    cat_kernel<<<dim3(Bsz / 128, NUM_CAT), 256>>>(x, w_lin, W_cat);

    // 1b. W split (bf16 hi/lo, padded [k][224])
    convert_w<<<(KPAD0 * NPAD + 255) / 256, 256>>>(cin_w0, p_W0hi, p_W0lo, 39 * 39, KPAD0);
    convert_w<<<(KPAD1 * NPAD + 255) / 256, 256>>>(cin_w1, p_W1hi, p_W1lo, 39 * 200, KPAD1);
    convert_w<<<(KPAD1 * NPAD + 255) / 256, 256>>>(cin_w2, p_W2hi, p_W2lo, 39 * 200, KPAD1);

    const int RGRID = (Rrows * 200 + 255) / 256;

    // 2. CIN layers (WMMA GEMMs, K-split) + reduces
    cin_wmma<39,  KPER0><<<dim3(Rrows / 128, SPLIT0), 256, SM0>>>(p_E_dm, p_W0hi, p_W0lo, p_part);
    reduce_kernel<<<RGRID, 256>>>(cin_b0, p_cin0, SPLIT0);
    cin_wmma<200, KPER1><<<dim3(Rrows / 128, SPLIT1), 256, SM1>>>(p_cin0, p_W1hi, p_W1lo, p_part);
    reduce_kernel<<<RGRID, 256>>>(cin_b1, p_cin1, SPLIT1);
    cin_wmma<200, KPER1><<<dim3(Rrows / 128, SPLIT1), 256, SM1>>>(p_cin1, p_W2hi, p_W2lo, p_part);
    reduce_kernel<<<RGRID, 256>>>(cin_b2, p_cin2, SPLIT1);

    // 3. CIN pooling + linear
    pool_kernel<<<Bsz, 256>>>(cin_lin_w);

    // 4. DNN
    dim3 dgrid(Bsz / 64, 400 / 40);
    dnn_gemm<<<dgrid, 256>>>(p_E_flat, dnn_w0, dnn_b0, p_h0, Mfld * Demb, 1);
    dnn_gemm<<<dgrid, 256>>>(p_h0, dnn_w1, dnn_b1, p_h1, 400, 1);

    // 5. final combine + sigmoid
    final_kernel<<<Bsz, 128>>>(b_lin, cin_lin_b, dnn_lin_w, dnn_lin_b, pred_b, out);
}

// round 6
// speedup vs baseline: 1.9861x; 1.1901x over previous
#include <cuda_runtime.h>
#include <cuda_bf16.h>
#include <math.h>
#include <stdint.h>

// ---------------------------------------------------------------------------
// xDeepFM forward. CIN via raw mma.sync bf16 3-term split, j-major K order:
//   k' = j*39 + i  (i: E field 0..38, j: C map 0..HIN-1)
//   A[r,k'] = E'[r,i]*C[r,j]  built directly in mma A-fragment registers.
//   W permuted+split to bf16 hi/lo [k'][224].
//   3 terms: AhiWhi + AhiWlo + AloWhi (fp32 accum). K-split across blocks.
// ---------------------------------------------------------------------------

#define Bsz 1024
#define NUM_NUMERIC 13
#define NUM_CAT 26
#define CARD 1000
#define Mfld 39
#define Demb 10
#define Ffeat 26013
#define Rrows (Bsz * Demb)   // 10240

#define NPAD 224
#define KPAD0 1536           // >= 39*39, 3 x 512
#define KPAD1 7840           // >= 39*200, 7 x 1120
#define SPLIT0 3
#define SPLIT1 7
#define KPER0 (KPAD0 / SPLIT0)   // 512  (32 ksteps)
#define KPER1 (KPAD1 / SPLIT1)   // 1120 (70 ksteps)
#define PSTR ((size_t)Rrows * NPAD)

// ----------------------------- scratch --------------------------------------
__device__ float g_E_dm[Rrows * Mfld];
__device__ float g_E_flat[Bsz * Mfld * Demb];
__device__ float g_linpart[27 * Bsz];
__device__ float g_part[SPLIT1 * Rrows * NPAD];
__device__ float g_cin0[Rrows * 200];
__device__ float g_cin1[Rrows * 200];
__device__ float g_cin2[Rrows * 200];
__device__ float g_cinlogit[Bsz];
__device__ float g_h0[Bsz * 400];
__device__ float g_h1[Bsz * 400];

__device__ __nv_bfloat16 g_W0hi[KPAD0 * NPAD];
__device__ __nv_bfloat16 g_W0lo[KPAD0 * NPAD];
__device__ __nv_bfloat16 g_W1hi[KPAD1 * NPAD];
__device__ __nv_bfloat16 g_W1lo[KPAD1 * NPAD];
__device__ __nv_bfloat16 g_W2hi[KPAD1 * NPAD];
__device__ __nv_bfloat16 g_W2lo[KPAD1 * NPAD];

// ----------------------------- helpers --------------------------------------
__device__ __forceinline__ uint32_t smem_u32(const void* p) {
    uint32_t a;
    asm("{ .reg .u64 t; cvta.to.shared.u64 t, %1; cvt.u32.u64 %0, t; }" : "=r"(a) : "l"(p));
    return a;
}
__device__ __forceinline__ void cp_async16g(void* dst, const void* src) {
    unsigned s = (unsigned)__cvta_generic_to_shared(dst);
    asm volatile("cp.async.cg.shared.global [%0], [%1], 16;\n" :: "r"(s), "l"(src));
}
#define CP_COMMIT() asm volatile("cp.async.commit_group;\n" ::: "memory")
#define CP_WAIT0()  asm volatile("cp.async.wait_group 0;\n" ::: "memory")

__device__ __forceinline__ void ldsm_x4_t(uint32_t& r0, uint32_t& r1, uint32_t& r2, uint32_t& r3,
                                          uint32_t saddr) {
    asm volatile("ldmatrix.sync.aligned.m8n8.x4.trans.shared.b16 {%0,%1,%2,%3}, [%4];"
                 : "=r"(r0), "=r"(r1), "=r"(r2), "=r"(r3) : "r"(saddr));
}
__device__ __forceinline__ void mma16816(float* c,
                                         uint32_t a0, uint32_t a1, uint32_t a2, uint32_t a3,
                                         uint32_t b0, uint32_t b1) {
    asm volatile("mma.sync.aligned.m16n8k16.row.col.f32.bf16.bf16.f32 "
                 "{%0,%1,%2,%3},{%4,%5,%6,%7},{%8,%9},{%0,%1,%2,%3};"
                 : "+f"(c[0]), "+f"(c[1]), "+f"(c[2]), "+f"(c[3])
                 : "r"(a0), "r"(a1), "r"(a2), "r"(a3), "r"(b0), "r"(b1));
}
__device__ __forceinline__ uint32_t pack_bf2(float x, float y) {
    __nv_bfloat16 hx = __float2bfloat16_rn(x);
    __nv_bfloat16 hy = __float2bfloat16_rn(y);
    return ((uint32_t)__bfloat16_as_ushort(hy) << 16) | __bfloat16_as_ushort(hx);
}

// ===========================================================================
// embeddings (numeric) + numeric linear partial
// ===========================================================================
__global__ void numeric_kernel(const float* __restrict__ x,
                               const float* __restrict__ w_lin,
                               const float* __restrict__ W_num) {
    const int b = blockIdx.x * 128 + threadIdx.x;
    const float* xr = x + (size_t)b * Ffeat;
    float lin = 0.0f;
    #pragma unroll
    for (int f = 0; f < NUM_NUMERIC; ++f) {
        float xv = xr[f];
        lin += xv * w_lin[f];
        #pragma unroll
        for (int d = 0; d < Demb; ++d) {
            float v = xv * W_num[f * Demb + d];
            g_E_flat[b * (Mfld * Demb) + f * Demb + d] = v;
            g_E_dm[(b * Demb + d) * Mfld + f] = v;
        }
    }
    g_linpart[26 * Bsz + b] = lin;
}

// ===========================================================================
// categorical embeddings (skinny GEMMs) + per-field linear partials
// ===========================================================================
__global__ __launch_bounds__(256)
void cat_kernel(const float* __restrict__ x,
                const float* __restrict__ w_lin,
                const float* __restrict__ W_cat) {
    __shared__ float Xs[64 * 130];
    __shared__ float Ws[64 * 10];
    __shared__ float Ls[64];

    const int t    = threadIdx.x;
    const int f    = blockIdx.y;
    const int b0   = blockIdx.x * 128;
    const int r    = t & 127;
    const int half = t >> 7;
    const int d0   = half * 5;

    float acc[5] = {0.f, 0.f, 0.f, 0.f, 0.f};
    float lin = 0.0f;

    for (int k0 = 0; k0 < CARD; k0 += 64) {
        const int kc = min(64, CARD - k0);
        __syncthreads();
        for (int idx = t; idx < 128 * 64; idx += 256) {
            int rr = idx >> 6, c = idx & 63;
            float v = (c < kc) ? x[(size_t)(b0 + rr) * Ffeat + NUM_NUMERIC + f * CARD + k0 + c] : 0.0f;
            Xs[c * 130 + rr] = v;
        }
        for (int idx = t; idx < 640; idx += 256) {
            int kk = idx / 10, d = idx - kk * 10;
            Ws[idx] = (kk < kc) ? W_cat[(size_t)(f * CARD + k0 + kk) * Demb + d] : 0.0f;
        }
        if (t < 64) Ls[t] = (t < kc) ? w_lin[NUM_NUMERIC + f * CARD + k0 + t] : 0.0f;
        __syncthreads();

        #pragma unroll 8
        for (int kk = 0; kk < 64; ++kk) {
            float xv = Xs[kk * 130 + r];
            if (half == 0) lin += xv * Ls[kk];
            #pragma unroll
            for (int q = 0; q < 5; ++q) acc[q] += xv * Ws[kk * 10 + d0 + q];
        }
    }

    const int b = b0 + r;
    const int fld = NUM_NUMERIC + f;
    #pragma unroll
    for (int q = 0; q < 5; ++q) {
        int d = d0 + q;
        g_E_flat[b * (Mfld * Demb) + fld * Demb + d] = acc[q];
        g_E_dm[(b * Demb + d) * Mfld + fld] = acc[q];
    }
    if (half == 0) g_linpart[f * Bsz + b] = lin;
}

// ===========================================================================
// W split to bf16 hi/lo, j-major permuted layout [k' = j*39+i][224]
// ===========================================================================
__global__ void convert_w(const float* __restrict__ W,
                          __nv_bfloat16* __restrict__ Whi,
                          __nv_bfloat16* __restrict__ Wlo,
                          int HIN, int KPAD) {
    int idx = blockIdx.x * 256 + threadIdx.x;
    if (idx >= KPAD * NPAD) return;
    int kp = idx / NPAD;
    int n  = idx - kp * NPAD;
    int j  = kp / 39;
    int i  = kp - j * 39;
    float v = (j < HIN && n < 200) ? W[(size_t)(i * HIN + j) * 200 + n] : 0.0f;
    __nv_bfloat16 h = __float2bfloat16_rn(v);
    Whi[idx] = h;
    Wlo[idx] = __float2bfloat16_rn(v - __bfloat162float(h));
}

// ===========================================================================
// CIN GEMM: raw mma.sync bf16 3-term split, A built in registers.
// Block 64 rows x 224 cols, 256 threads = 8 warps (wm 4 x wn 2),
// warp tile 16m x 112n. K-split via blockIdx.y.  2 blocks/SM target.
// ===========================================================================
template <int HIN, int KPER, int JS>
__global__ void __launch_bounds__(256, 2)
cin_mma(const float* __restrict__ Cmat,
        const __nv_bfloat16* __restrict__ Whi,
        const __nv_bfloat16* __restrict__ Wlo,
        float* __restrict__ part) {
    constexpr int NK     = KPER / 16;
    constexpr int CSTR   = JS + 1;                       // odd stride, conflict-free
    constexpr int ES_OFF = 64 * CSTR * 4;
    constexpr int B_OFF  = ((ES_OFF + 64 * 39 * 4 + 15) / 16) * 16;
    constexpr int B_HALF = 16 * 232 * 2;                 // 7424 B (n-stride 232)
    constexpr int B_STRIDE = 2 * B_HALF;                 // hi+lo per buffer

    extern __shared__ char sm[];
    float* Cs = (float*)sm;
    float* Es = (float*)(sm + ES_OFF);
    const uint32_t smb = smem_u32(sm);

    const int tid  = threadIdx.x;
    const int lane = tid & 31;
    const int wid  = tid >> 5;
    const int wm   = wid & 3;
    const int wn   = wid >> 2;
    const int g    = lane >> 2;
    const int tig  = lane & 3;
    const int row0 = blockIdx.x * 64;
    const int kbase = blockIdx.y * KPER;
    const int jbase = kbase / 39;

    // resident tiles
    for (int idx = tid; idx < 64 * JS; idx += 256) {
        int m = idx / JS, jj = idx - m * JS;
        int j = jbase + jj;
        Cs[m * CSTR + jj] = (j < HIN) ? Cmat[(size_t)(row0 + m) * HIN + j] : 0.0f;
    }
    for (int idx = tid; idx < 64 * 39; idx += 256) {
        int m = idx / 39, i = idx - m * 39;
        Es[m * 39 + i] = g_E_dm[(size_t)(row0 + m) * 39 + i];
    }

    auto load_B = [&](int ks, int buf) {
        char* base = sm + B_OFF + buf * B_STRIDE;
        const int kr0 = kbase + ks * 16;
        for (int idx = tid; idx < 896; idx += 256) {
            int half = (idx >= 448) ? 1 : 0;
            int rem  = idx - half * 448;
            int kk   = rem / 28;
            int q    = rem - kk * 28;
            const __nv_bfloat16* src = (half ? Wlo : Whi) + (size_t)(kr0 + kk) * NPAD + q * 8;
            cp_async16g(base + half * B_HALF + kk * 464 + q * 16, src);
        }
        CP_COMMIT();
    };

    load_B(0, 0);
    CP_WAIT0();
    __syncthreads();

    float acc[14][4];
    #pragma unroll
    for (int p = 0; p < 14; ++p)
        #pragma unroll
        for (int q = 0; q < 4; ++q) acc[p][q] = 0.0f;

    const int m0 = wm * 16 + g;
    const int m1 = m0 + 8;
    // ldmatrix per-lane base offset within a B half-buffer
    const uint32_t lB = (uint32_t)(((lane & 7) + ((lane >> 3) & 1) * 8) * 464
                                   + ((lane >> 4) * 8) * 2 + wn * 224);

    for (int ks = 0; ks < NK; ++ks) {
        const int buf = ks & 1;
        if (ks + 1 < NK) load_B(ks + 1, buf ^ 1);

        // ---- build A fragments (hi/lo) in registers ----
        uint32_t ah[4], al[4];
        {
            const int k0 = kbase + ks * 16;
            float v0[4], v1[4];
            #pragma unroll
            for (int q = 0; q < 4; ++q) {
                int kk = tig * 2 + (q & 1) + (q >> 1) * 8;
                int kg = k0 + kk;
                int j  = kg / 39;
                int i  = kg - j * 39;
                int jj = j - jbase;
                float e0 = Es[m0 * 39 + i], c0 = Cs[m0 * CSTR + jj];
                float e1 = Es[m1 * 39 + i], c1 = Cs[m1 * CSTR + jj];
                v0[q] = e0 * c0;
                v1[q] = e1 * c1;
            }
            float h00 = __bfloat162float(__float2bfloat16_rn(v0[0]));
            float h01 = __bfloat162float(__float2bfloat16_rn(v0[1]));
            float h02 = __bfloat162float(__float2bfloat16_rn(v0[2]));
            float h03 = __bfloat162float(__float2bfloat16_rn(v0[3]));
            float h10 = __bfloat162float(__float2bfloat16_rn(v1[0]));
            float h11 = __bfloat162float(__float2bfloat16_rn(v1[1]));
            float h12 = __bfloat162float(__float2bfloat16_rn(v1[2]));
            float h13 = __bfloat162float(__float2bfloat16_rn(v1[3]));
            ah[0] = pack_bf2(h00, h01);
            ah[1] = pack_bf2(h10, h11);
            ah[2] = pack_bf2(h02, h03);
            ah[3] = pack_bf2(h12, h13);
            al[0] = pack_bf2(v0[0] - h00, v0[1] - h01);
            al[1] = pack_bf2(v1[0] - h10, v1[1] - h11);
            al[2] = pack_bf2(v0[2] - h02, v0[3] - h03);
            al[3] = pack_bf2(v1[2] - h12, v1[3] - h13);
        }

        // ---- MMAs over 7 n-tiles ----
        const uint32_t bs = smb + B_OFF + buf * B_STRIDE + lB;
        #pragma unroll
        for (int nt = 0; nt < 7; ++nt) {
            uint32_t r0, r1, r2, r3, s0, s1, s2, s3;
            ldsm_x4_t(r0, r1, r2, r3, bs + nt * 32);                 // Bhi
            ldsm_x4_t(s0, s1, s2, s3, bs + B_HALF + nt * 32);        // Blo
            mma16816(acc[nt * 2],     ah[0], ah[1], ah[2], ah[3], r0, r1);
            mma16816(acc[nt * 2 + 1], ah[0], ah[1], ah[2], ah[3], r2, r3);
            mma16816(acc[nt * 2],     ah[0], ah[1], ah[2], ah[3], s0, s1);
            mma16816(acc[nt * 2 + 1], ah[0], ah[1], ah[2], ah[3], s2, s3);
            mma16816(acc[nt * 2],     al[0], al[1], al[2], al[3], r0, r1);
            mma16816(acc[nt * 2 + 1], al[0], al[1], al[2], al[3], r2, r3);
        }

        CP_WAIT0();
        __syncthreads();
    }

    // ---- epilogue: store partials ----
    float* op = part + (size_t)blockIdx.y * PSTR;
    #pragma unroll
    for (int nt = 0; nt < 7; ++nt)
        #pragma unroll
        for (int nh = 0; nh < 2; ++nh) {
            const float* c = acc[nt * 2 + nh];
            int col = wn * 112 + nt * 16 + nh * 8 + tig * 2;
            size_t r = (size_t)(row0 + wm * 16 + g);
            *(float2*)&op[r * NPAD + col]       = make_float2(c[0], c[1]);
            *(float2*)&op[(r + 8) * NPAD + col] = make_float2(c[2], c[3]);
        }
}

// ===========================================================================
// Reduce K-split partials (+bias) into the 200-wide layer output.
// ===========================================================================
__global__ void reduce_kernel(const float* __restrict__ bias,
                              float* __restrict__ dst, int S) {
    int idx = blockIdx.x * 256 + threadIdx.x;
    if (idx >= Rrows * 200) return;
    int r = idx / 200;
    int h = idx - r * 200;
    float v = bias[h];
    for (int s = 0; s < S; ++s) v += g_part[(size_t)s * PSTR + (size_t)r * NPAD + h];
    dst[idx] = v;
}

// ===========================================================================
// CIN pooling + cin linear
// ===========================================================================
__global__ void pool_kernel(const float* __restrict__ cin_lin_w) {
    const int b = blockIdx.x;
    const int tid = threadIdx.x;
    const float* outs[3];
    outs[0] = g_cin0; outs[1] = g_cin1; outs[2] = g_cin2;

    float acc = 0.0f;
    for (int j = tid; j < 3 * Demb * 200; j += 256) {
        int l = j / 2000;
        int rem = j - l * 2000;
        int d = rem / 200;
        int h = rem - d * 200;
        acc += outs[l][(size_t)(b * Demb + d) * 200 + h] * cin_lin_w[l * 200 + h];
    }
    __shared__ float red[256];
    red[tid] = acc;
    __syncthreads();
    for (int s = 128; s > 0; s >>= 1) {
        if (tid < s) red[tid] += red[tid + s];
        __syncthreads();
    }
    if (tid == 0) g_cinlogit[b] = red[0];
}

// ===========================================================================
// DNN GEMM + optional relu
// ===========================================================================
__global__ void dnn_gemm(const float* __restrict__ A,
                         const float* __restrict__ W,
                         const float* __restrict__ bias,
                         float* __restrict__ Out,
                         int K, int relu) {
    __shared__ float As[16 * 64];
    __shared__ float Bs[16 * 40];

    const int tid = threadIdx.x;
    const int row0 = blockIdx.x * 64;
    const int n0 = blockIdx.y * 40;
    const int tx = tid & 7;
    const int ty = tid >> 3;
    const int N = 400;

    float acc[2][5];
    #pragma unroll
    for (int m = 0; m < 2; ++m)
        #pragma unroll
        for (int q = 0; q < 5; ++q) acc[m][q] = 0.0f;

    for (int k0 = 0; k0 < K; k0 += 16) {
        __syncthreads();
        for (int idx = tid; idx < 64 * 16; idx += 256) {
            int r = idx >> 4, kk = idx & 15;
            int k = k0 + kk;
            As[kk * 64 + r] = (k < K) ? A[(size_t)(row0 + r) * K + k] : 0.0f;
        }
        for (int idx = tid; idx < 16 * 40; idx += 256) {
            int kk = idx / 40, q = idx - kk * 40;
            int k = k0 + kk;
            Bs[kk * 40 + q] = (k < K) ? W[(size_t)k * N + n0 + q] : 0.0f;
        }
        __syncthreads();

        #pragma unroll
        for (int kk = 0; kk < 16; ++kk) {
            float a0 = As[kk * 64 + ty * 2 + 0];
            float a1 = As[kk * 64 + ty * 2 + 1];
            float wv[5];
            #pragma unroll
            for (int q = 0; q < 5; ++q) wv[q] = Bs[kk * 40 + tx * 5 + q];
            #pragma unroll
            for (int q = 0; q < 5; ++q) {
                acc[0][q] += a0 * wv[q];
                acc[1][q] += a1 * wv[q];
            }
        }
    }

    #pragma unroll
    for (int m = 0; m < 2; ++m) {
        int r = row0 + ty * 2 + m;
        #pragma unroll
        for (int q = 0; q < 5; ++q) {
            int n = n0 + tx * 5 + q;
            float v = acc[m][q] + bias[n];
            if (relu) v = fmaxf(v, 0.0f);
            Out[(size_t)r * N + n] = v;
        }
    }
}

// ===========================================================================
// Final: dnn linear dot + linear partials + combine + sigmoid
// ===========================================================================
__global__ void final_kernel(const float* __restrict__ b_lin,
                             const float* __restrict__ cin_lin_b,
                             const float* __restrict__ dnn_lin_w,
                             const float* __restrict__ dnn_lin_b,
                             const float* __restrict__ pred_b,
                             float* __restrict__ out) {
    const int b = blockIdx.x;
    const int tid = threadIdx.x;
    float acc = 0.0f;
    for (int k = tid; k < 400; k += 128)
        acc += g_h1[(size_t)b * 400 + k] * dnn_lin_w[k];
    for (int f = tid; f < 27; f += 128)
        acc += g_linpart[f * Bsz + b];
    __shared__ float red[128];
    red[tid] = acc;
    __syncthreads();
    for (int s = 64; s > 0; s >>= 1) {
        if (tid < s) red[tid] += red[tid + s];
        __syncthreads();
    }
    if (tid == 0) {
        float z = red[0] + b_lin[0]
                + g_cinlogit[b] + cin_lin_b[0]
                + dnn_lin_b[0] + pred_b[0];
        out[b] = 1.0f / (1.0f + expf(-z));
    }
}

// ===========================================================================
// host launcher
// ===========================================================================
static int smem_cin(int JS) {
    int cstr = JS + 1;
    int es_off = 64 * cstr * 4;
    int b_off = ((es_off + 64 * 39 * 4 + 15) / 16) * 16;
    return b_off + 2 * (2 * 16 * 232 * 2);
}

extern "C" void kernel_launch(void* const* d_in, const int* in_sizes, int n_in,
                              void* d_out, int out_size) {
    const float* x         = (const float*)d_in[0];
    const float* w_lin     = (const float*)d_in[1];
    const float* b_lin     = (const float*)d_in[2];
    const float* W_num     = (const float*)d_in[3];
    const float* W_cat     = (const float*)d_in[4];
    const float* cin_w0    = (const float*)d_in[5];
    const float* cin_b0    = (const float*)d_in[6];
    const float* cin_w1    = (const float*)d_in[7];
    const float* cin_b1    = (const float*)d_in[8];
    const float* cin_w2    = (const float*)d_in[9];
    const float* cin_b2    = (const float*)d_in[10];
    const float* cin_lin_w = (const float*)d_in[11];
    const float* cin_lin_b = (const float*)d_in[12];
    const float* dnn_w0    = (const float*)d_in[13];
    const float* dnn_b0    = (const float*)d_in[14];
    const float* dnn_w1    = (const float*)d_in[15];
    const float* dnn_b1    = (const float*)d_in[16];
    const float* dnn_lin_w = (const float*)d_in[17];
    const float* dnn_lin_b = (const float*)d_in[18];
    const float* pred_b    = (const float*)d_in[19];
    float* out = (float*)d_out;

    float *p_E_dm, *p_cin0, *p_cin1, *p_cin2, *p_E_flat, *p_h0, *p_h1, *p_part;
    cudaGetSymbolAddress((void**)&p_E_dm,   g_E_dm);
    cudaGetSymbolAddress((void**)&p_E_flat, g_E_flat);
    cudaGetSymbolAddress((void**)&p_cin0,   g_cin0);
    cudaGetSymbolAddress((void**)&p_cin1,   g_cin1);
    cudaGetSymbolAddress((void**)&p_cin2,   g_cin2);
    cudaGetSymbolAddress((void**)&p_h0,     g_h0);
    cudaGetSymbolAddress((void**)&p_h1,     g_h1);
    cudaGetSymbolAddress((void**)&p_part,   g_part);

    __nv_bfloat16 *p_W0hi, *p_W0lo, *p_W1hi, *p_W1lo, *p_W2hi, *p_W2lo;
    cudaGetSymbolAddress((void**)&p_W0hi, g_W0hi);
    cudaGetSymbolAddress((void**)&p_W0lo, g_W0lo);
    cudaGetSymbolAddress((void**)&p_W1hi, g_W1hi);
    cudaGetSymbolAddress((void**)&p_W1lo, g_W1lo);
    cudaGetSymbolAddress((void**)&p_W2hi, g_W2hi);
    cudaGetSymbolAddress((void**)&p_W2lo, g_W2lo);

    // j-window sizes: KPER/39 rounded up +1
    const int SM0 = smem_cin(14);   // layer0: KPER 512  -> 14 cols
    const int SM1 = smem_cin(30);   // layers 1/2: KPER 1120 -> 30 cols
    cudaFuncSetAttribute(cin_mma<39,  KPER0, 14>, cudaFuncAttributeMaxDynamicSharedMemorySize, SM0);
    cudaFuncSetAttribute(cin_mma<200, KPER1, 30>, cudaFuncAttributeMaxDynamicSharedMemorySize, SM1);

    // 1. embeddings + linear partials
    numeric_kernel<<<Bsz / 128, 128>>>(x, w_lin, W_num);
    cat_kernel<<<dim3(Bsz / 128, NUM_CAT), 256>>>(x, w_lin, W_cat);

    // 1b. W split (bf16 hi/lo, j-major permuted [k'][224])
    convert_w<<<(KPAD0 * NPAD + 255) / 256, 256>>>(cin_w0, p_W0hi, p_W0lo, 39,  KPAD0);
    convert_w<<<(KPAD1 * NPAD + 255) / 256, 256>>>(cin_w1, p_W1hi, p_W1lo, 200, KPAD1);
    convert_w<<<(KPAD1 * NPAD + 255) / 256, 256>>>(cin_w2, p_W2hi, p_W2lo, 200, KPAD1);

    const int RGRID = (Rrows * 200 + 255) / 256;
    const int ROWB = Rrows / 64;   // 160

    // 2. CIN layers + reduces
    cin_mma<39,  KPER0, 14><<<dim3(ROWB, SPLIT0), 256, SM0>>>(p_E_dm, p_W0hi, p_W0lo, p_part);
    reduce_kernel<<<RGRID, 256>>>(cin_b0, p_cin0, SPLIT0);
    cin_mma<200, KPER1, 30><<<dim3(ROWB, SPLIT1), 256, SM1>>>(p_cin0, p_W1hi, p_W1lo, p_part);
    reduce_kernel<<<RGRID, 256>>>(cin_b1, p_cin1, SPLIT1);
    cin_mma<200, KPER1, 30><<<dim3(ROWB, SPLIT1), 256, SM1>>>(p_cin1, p_W2hi, p_W2lo, p_part);
    reduce_kernel<<<RGRID, 256>>>(cin_b2, p_cin2, SPLIT1);

    // 3. CIN pooling + linear
    pool_kernel<<<Bsz, 256>>>(cin_lin_w);

    // 4. DNN
    dim3 dgrid(Bsz / 64, 400 / 40);
    dnn_gemm<<<dgrid, 256>>>(p_E_flat, dnn_w0, dnn_b0, p_h0, Mfld * Demb, 1);
    dnn_gemm<<<dgrid, 256>>>(p_h0, dnn_w1, dnn_b1, p_h1, 400, 1);

    // 5. final combine + sigmoid
    final_kernel<<<Bsz, 128>>>(b_lin, cin_lin_b, dnn_lin_w, dnn_lin_b, pred_b, out);
}